// round 13
// baseline (speedup 1.0000x reference)
#include <cuda_runtime.h>

#define FULL 0xFFFFFFFFu

// Problem constants
#define BATCH 32
#define IN    2048
#define OUT   2048
#define KNUM  8
#define HDIM  512
#define KSZ   (IN * OUT)          // 4M elements per expert

#define IBLK   256                // i-range per main block
#define NCHUNK (IN / IBLK)        // 8
#define OBLK   32                 // o's per block
#define NOBLK  (OUT / OBLK)       // 64
#define QI     64                 // i per pipeline stage
#define NQ     (IBLK / QI)        // 4 stages per block
#define STAGE_FLOATS (KNUM * OBLK * QI)   // 16384 floats = 64 KB
#define XS_FLOATS    (BATCH * IBLK)       // 8192 floats  = 32 KB
#define SMEM_MAIN    ((XS_FLOATS + 3 * STAGE_FLOATS) * 4)   // 229376 B

// Scratch (device globals; returned to initial state every call -> replay safe)
__device__ float    g_h[HDIM];
__device__ unsigned g_ticket;
__device__ float    g_alpha[KNUM];

// ---------------------------------------------------------------------------
// Fused MLP (single launch, proven): partial cond@w1 -> atomic into g_h;
// zero out-slice; last block finishes relu/w2/softmax; resets scratch.
// ---------------------------------------------------------------------------
__global__ void mlp_kernel(const float* __restrict__ cond,
                           const float* __restrict__ w1,
                           const float* __restrict__ b1,
                           const float* __restrict__ w2,
                           const float* __restrict__ b2,
                           float* __restrict__ out) {
    __shared__ float    h_s[HDIM];
    __shared__ float    s_s[KNUM];
    __shared__ unsigned rank_s;

    int j  = threadIdx.x;         // 0..511
    int p  = blockIdx.x;          // 0..127
    int i0 = p * 16;

    float s[8];
#pragma unroll
    for (int u = 0; u < 8; ++u)
        s[u] = cond[i0 + u] * w1[(i0 + u) * HDIM + j];
#pragma unroll
    for (int u = 0; u < 8; ++u)
        s[u] += cond[i0 + 8 + u] * w1[(i0 + 8 + u) * HDIM + j];
    float sum = ((s[0] + s[1]) + (s[2] + s[3])) + ((s[4] + s[5]) + (s[6] + s[7]));

    atomicAdd(&g_h[j], sum);
    out[p * HDIM + j] = 0.f;

    __threadfence();
    __syncthreads();
    if (j == 0) rank_s = atomicAdd(&g_ticket, 1u);
    __syncthreads();
    if (rank_s != gridDim.x - 1) return;

    __threadfence();
    h_s[j] = fmaxf(g_h[j] + b1[j], 0.f);
    __syncthreads();

    int wid = j >> 5, lane = j & 31;
    if (wid < KNUM) {
        float sc = 0.f;
#pragma unroll
        for (int m = 0; m < HDIM / 32; ++m) {
            int jj = lane + m * 32;
            sc += h_s[jj] * w2[jj * KNUM + wid];
        }
#pragma unroll
        for (int off = 16; off; off >>= 1) sc += __shfl_xor_sync(FULL, sc, off);
        if (lane == 0) s_s[wid] = sc + b2[wid];
    }
    __syncthreads();
    if (j == 0) {
        float mx = -1e30f;
#pragma unroll
        for (int k = 0; k < KNUM; ++k) mx = fmaxf(mx, s_s[k]);
        float e[KNUM];
        float ssum = 0.f;
#pragma unroll
        for (int k = 0; k < KNUM; ++k) { e[k] = __expf(s_s[k] - mx); ssum += e[k]; }
        float inv = 1.f / ssum;
#pragma unroll
        for (int k = 0; k < KNUM; ++k) g_alpha[k] = e[k] * inv;
        g_ticket = 0;
    }
    g_h[j] = 0.f;
}

// ---------------------------------------------------------------------------
// cp.async helpers
// ---------------------------------------------------------------------------
__device__ __forceinline__ void cp_async16(unsigned dst, const void* src) {
    asm volatile("cp.async.cg.shared.global [%0], [%1], 16;"
                 :: "r"(dst), "l"(src));
}
#define CP_COMMIT()  asm volatile("cp.async.commit_group;" ::: "memory")
#define CP_WAIT(n)   asm volatile("cp.async.wait_group %0;" :: "n"(n) : "memory")

// ---------------------------------------------------------------------------
// Main: out[b,o] (+)= sum_{i in chunk} (sum_k a_k KW[k,o,i]) * x[b,i]
// grid = NCHUNK*NOBLK = 512 blocks x 256 threads, 1 block/SM (224 KB smem).
// kw staged via cp.async.cg into a 3-deep smem pipeline (192 KB in flight
// per SM, no registers). Thread = (oi = wid*2+og, io 4-i slice); owns
// o_lo=oi, o_hi=oi+16, FULL batch (acc 2x32). x reads og-broadcast-deduped.
// Epilogue: shuffle-reduce over io, 2 writer lanes/warp atomicAdd.
// ---------------------------------------------------------------------------
__global__ __launch_bounds__(256) void main_kernel(
        const float* __restrict__ x,    // [32, 2048]
        const float* __restrict__ kw,   // [8, 2048, 2048]
        const float* __restrict__ kb,   // [8, 2048]
        float* __restrict__ out) {      // [32, 2048]
    extern __shared__ float sm[];
    float* x_s = sm;                    // [b*256 + i], 32 KB
    // kw stage s: sm + XS_FLOATS + s*STAGE_FLOATS, layout [(k*32+ol)*64 + i]

    int t    = threadIdx.x;
    int wid  = t >> 5;
    int lane = t & 31;
    int io   = lane & 15;
    int og   = lane >> 4;
    int ob   = blockIdx.x & (NOBLK - 1);          // 0..63
    int c    = blockIdx.x >> 6;                   // 0..7
    int i0   = c * IBLK;
    int o_base = ob * OBLK;
    int oi   = wid * 2 + og;                      // 0..15
    int o_lo = o_base + oi;
    int o_hi = o_base + oi + 16;

    unsigned smem_u32 =
        (unsigned)__cvta_generic_to_shared(sm);
    unsigned kwst_u32 = smem_u32 + XS_FLOATS * 4;

    // ---- issue stages 0..2 (fills DRAM queue before anything else) ----
#pragma unroll
    for (int s = 0; s < 3; ++s) {
#pragma unroll
        for (int j = 0; j < 16; ++j) {
            int e  = j * 256 + t;                 // 0..4095
            int k  = e >> 9;
            int ol = (e >> 4) & 31;
            int ie = e & 15;
            const float* src = kw + (size_t)k * KSZ +
                               (size_t)(o_base + ol) * IN + i0 + s * QI + ie * 4;
            cp_async16(kwst_u32 + (unsigned)(s * STAGE_FLOATS + e * 4) * 4u, src);
        }
        CP_COMMIT();
    }

    // ---- stage x while the pipeline fills ----
    const float4* x4 = reinterpret_cast<const float4*>(x);
#pragma unroll
    for (int jj = 0; jj < XS_FLOATS / (4 * 256); ++jj) {
        int idx = jj * 256 + t;                   // 0..2047 float4 units
        int b   = idx >> 6;                       // 64 f4 per row
        int il4 = idx & 63;
        *reinterpret_cast<float4*>(&x_s[b * IBLK + il4 * 4]) =
            x4[(b * IN + i0) / 4 + il4];
    }

    float a[KNUM];
#pragma unroll
    for (int k = 0; k < KNUM; ++k) a[k] = g_alpha[k];

    __syncthreads();   // x_s visible to all

    float acc_lo[BATCH], acc_hi[BATCH];
#pragma unroll
    for (int b = 0; b < BATCH; ++b) { acc_lo[b] = 0.f; acc_hi[b] = 0.f; }

#pragma unroll
    for (int q = 0; q < NQ; ++q) {
        int buf = q % 3;

        // wait for stage q's group: outstanding groups afterwards
        if (q == 0)      CP_WAIT(2);
        else if (q == 1) CP_WAIT(2);
        else if (q == 2) CP_WAIT(1);
        else             CP_WAIT(0);
        __syncthreads();                          // all threads' copies visible

        // ---- aggregate experts for this thread's 2 o's (from smem) ----
        const float* ks = sm + XS_FLOATS + buf * STAGE_FLOATS;
        float4 wlo, whi;
        {
            float4 v = *reinterpret_cast<const float4*>(
                           ks + (0 * OBLK + oi) * QI + io * 4);
            float4 u = *reinterpret_cast<const float4*>(
                           ks + (0 * OBLK + oi + 16) * QI + io * 4);
            wlo.x = a[0] * v.x; wlo.y = a[0] * v.y;
            wlo.z = a[0] * v.z; wlo.w = a[0] * v.w;
            whi.x = a[0] * u.x; whi.y = a[0] * u.y;
            whi.z = a[0] * u.z; whi.w = a[0] * u.w;
        }
#pragma unroll
        for (int k = 1; k < KNUM; ++k) {
            float4 v = *reinterpret_cast<const float4*>(
                           ks + (k * OBLK + oi) * QI + io * 4);
            float4 u = *reinterpret_cast<const float4*>(
                           ks + (k * OBLK + oi + 16) * QI + io * 4);
            float ak = a[k];
            wlo.x += ak * v.x; wlo.y += ak * v.y;
            wlo.z += ak * v.z; wlo.w += ak * v.w;
            whi.x += ak * u.x; whi.y += ak * u.y;
            whi.z += ak * u.z; whi.w += ak * u.w;
        }

        // ---- refill: stage q+3 reuses this buffer (only q==0 here) ----
        if (q == 0) {
            __syncthreads();                      // everyone done reading buf 0
#pragma unroll
            for (int j = 0; j < 16; ++j) {
                int e  = j * 256 + t;
                int k  = e >> 9;
                int ol = (e >> 4) & 31;
                int ie = e & 15;
                const float* src = kw + (size_t)k * KSZ +
                                   (size_t)(o_base + ol) * IN + i0 + 3 * QI + ie * 4;
                cp_async16(kwst_u32 + (unsigned)(e * 4) * 4u, src);
            }
            CP_COMMIT();
        }

        // ---- compute: full batch, x og-broadcast, w in regs ----
        const float* xr = x_s + q * QI + io * 4;
#pragma unroll
        for (int b = 0; b < BATCH; ++b) {
            float4 xq = *reinterpret_cast<const float4*>(xr + b * IBLK);
            acc_lo[b] += wlo.x * xq.x; acc_lo[b] += wlo.y * xq.y;
            acc_lo[b] += wlo.z * xq.z; acc_lo[b] += wlo.w * xq.w;
            acc_hi[b] += whi.x * xq.x; acc_hi[b] += whi.y * xq.y;
            acc_hi[b] += whi.z * xq.z; acc_hi[b] += whi.w * xq.w;
        }
    }

    // ---- epilogue: reduce over io via shuffles, 2 writer lanes/warp ----
    float bias_lo = 0.f, bias_hi = 0.f;
    if (c == 0) {
#pragma unroll
        for (int k = 0; k < KNUM; ++k) {
            bias_lo += a[k] * kb[k * OUT + o_lo];
            bias_hi += a[k] * kb[k * OUT + o_hi];
        }
    }
#pragma unroll
    for (int b = 0; b < BATCH; ++b) {
        float vlo = acc_lo[b];
        float vhi = acc_hi[b];
#pragma unroll
        for (int off = 8; off; off >>= 1) {
            vlo += __shfl_xor_sync(FULL, vlo, off);
            vhi += __shfl_xor_sync(FULL, vhi, off);
        }
        if (io == 0) {
            atomicAdd(&out[b * OUT + o_lo], vlo + bias_lo);
            atomicAdd(&out[b * OUT + o_hi], vhi + bias_hi);
        }
    }
}

// ---------------------------------------------------------------------------
extern "C" void kernel_launch(void* const* d_in, const int* in_sizes, int n_in,
                              void* d_out, int out_size) {
    const float* x    = (const float*)d_in[0];
    const float* cond = (const float*)d_in[1];
    const float* w1   = (const float*)d_in[2];
    const float* b1   = (const float*)d_in[3];
    const float* w2   = (const float*)d_in[4];
    const float* b2   = (const float*)d_in[5];
    const float* kw   = (const float*)d_in[6];
    const float* kb   = (const float*)d_in[7];
    float* out = (float*)d_out;

    static int smem_set = 0;
    if (!smem_set) {
        cudaFuncSetAttribute(main_kernel,
                             cudaFuncAttributeMaxDynamicSharedMemorySize,
                             SMEM_MAIN);
        smem_set = 1;
    }

    mlp_kernel<<<128, HDIM>>>(cond, w1, b1, w2, b2, out);
    main_kernel<<<NCHUNK * NOBLK, 256, SMEM_MAIN>>>(x, kw, kb, out);
}